// round 4
// baseline (speedup 1.0000x reference)
#include <cuda_runtime.h>

#define D_ 4
#define R_ 32
#define F_ 8
#define U_ 64
#define B_ 512

typedef unsigned long long ull;

// ---------- packed f32x2 helpers (SASS FFMA2) ----------
static __device__ __forceinline__ ull pk2(float lo, float hi) {
    ull r; asm("mov.b64 %0, {%1, %2};" : "=l"(r) : "f"(lo), "f"(hi)); return r;
}
static __device__ __forceinline__ void upk2(ull v, float& lo, float& hi) {
    asm("mov.b64 {%0, %1}, %2;" : "=f"(lo), "=f"(hi) : "l"(v));
}
static __device__ __forceinline__ ull fma2_(ull a, ull b, ull c) {
    ull d; asm("fma.rn.f32x2 %0, %1, %2, %3;" : "=l"(d) : "l"(a), "l"(b), "l"(c)); return d;
}
static __device__ __forceinline__ ull mul2_(ull a, ull b) {
    ull d; asm("mul.rn.f32x2 %0, %1, %2;" : "=l"(d) : "l"(a), "l"(b)); return d;
}

// Pair-merged products: g_KK[u][p][c=(d0*4+d1)][j*32+k]
__device__ float g_KK[U_ * 4 * 16 * 1024];   // 16 MB

// ---------------------------------------------------------------------------
// Precompute: 256 blocks = (u,p), 512 threads = 16 warps, warp w computes c=w.
// ---------------------------------------------------------------------------
__global__ __launch_bounds__(512) void kk_precompute(const float* __restrict__ K) {
    __shared__ float As[4][33 * 32];
    __shared__ float Bs[4][1024];
    const int u = blockIdx.x >> 2;
    const int p = blockIdx.x & 3;
    const int tid = threadIdx.x;

    for (int d = 0; d < 4; d++)
        for (int e = tid; e < 1024; e += 512) {
            As[d][(e >> 5) * 33 + (e & 31)] = K[((d * 1024 + e) * 8 + 2 * p) * 64 + u];
            Bs[d][e]                        = K[((d * 1024 + e) * 8 + 2 * p + 1) * 64 + u];
        }
    __syncthreads();

    const int c = tid >> 5, lane = tid & 31;
    const int d0 = c >> 2, d1 = c & 3;
    ull acc[16];
    #pragma unroll
    for (int q = 0; q < 16; q++) acc[q] = 0ull;
    const float* arow = &As[d0][lane * 33];
    const ulonglong2* bmat = (const ulonglong2*)Bs[d1];
    #pragma unroll
    for (int j = 0; j < 32; j++) {
        const ull a2 = pk2(arow[j], arow[j]);
        #pragma unroll
        for (int q = 0; q < 8; q++) {
            const ulonglong2 bv = bmat[j * 8 + q];   // broadcast
            acc[2 * q]     = fma2_(a2, bv.x, acc[2 * q]);
            acc[2 * q + 1] = fma2_(a2, bv.y, acc[2 * q + 1]);
        }
    }
    float4* dst = (float4*)(g_KK + (((u * 4 + p) * 16 + c) * 1024) + lane * 32);
    #pragma unroll
    for (int q = 0; q < 8; q++) {
        float4 o;
        upk2(acc[2 * q],     o.x, o.y);
        upk2(acc[2 * q + 1], o.z, o.w);
        dst[q] = o;
    }
}

// ---------------------------------------------------------------------------
// Main. Block = 256 threads = 8 warps, one u, 8 b (warp w owns b = b0+w).
// Smem (floats): Xs[256] | W[512] | SL[8*1152] | SR[8*1152] | As[8*1152]
// S0,S1,S3,A stored pitch 36 (float4 rows); S2 stored TRANSPOSED pitch 33.
// ---------------------------------------------------------------------------
#define PITCH 36
#define SLOT  1152            // 32*36 per b
#define OFF_W   256
#define OFF_SL  768
#define OFF_SR  (OFF_SL + 8 * SLOT)
#define OFF_AS  (OFF_SR + 8 * SLOT)
#define SMEM_FLOATS (OFF_AS + 8 * SLOT)

// Build S_p for all 8 b's. MODE 0: pitch-36 float4 row-major.
// MODE 1: transposed, pitch-33, scalar stores (for S2).
template <int MODE>
static __device__ __forceinline__ void build_stage(int u, int p, int tid,
                                                   const float* Wsm, float* dst) {
    const ulonglong2* kkbase =
        (const ulonglong2*)(g_KK + (size_t)((u * 4 + p) * 16) * 1024);
    ulonglong2 kk[16];
    #pragma unroll
    for (int c = 0; c < 16; c++) kk[c] = kkbase[c * 256 + tid];   // coalesced

    const int j = tid >> 3, k4 = tid & 7;
    #pragma unroll 2
    for (int b = 0; b < 8; b++) {
        float4 wv[4];
        #pragma unroll
        for (int q = 0; q < 4; q++)
            wv[q] = ((const float4*)(Wsm + (b * 4 + p) * 16))[q];   // broadcast
        const float* wf = (const float*)wv;
        ull accx = 0ull, accy = 0ull;
        #pragma unroll
        for (int c = 0; c < 16; c++) {
            const ull w2 = pk2(wf[c], wf[c]);
            accx = fma2_(w2, kk[c].x, accx);
            accy = fma2_(w2, kk[c].y, accy);
        }
        if (MODE == 0) {
            float4 o;
            upk2(accx, o.x, o.y); upk2(accy, o.z, o.w);
            *(float4*)(dst + b * SLOT + j * PITCH + 4 * k4) = o;
        } else {
            float s0, s1, s2, s3;
            upk2(accx, s0, s1); upk2(accy, s2, s3);
            float* base = dst + b * SLOT + j;          // transposed: [col][row]
            base[(4 * k4 + 0) * 33] = s0;
            base[(4 * k4 + 1) * 33] = s1;
            base[(4 * k4 + 2) * 33] = s2;
            base[(4 * k4 + 3) * 33] = s3;
        }
    }
}

// Register-tiled 32x32x32 matmul: C = A @ B, both operands pitch-36 in smem.
// Lane (r = lane>>2, c = lane&3) computes rows {r,r+8,r+16,r+24} x cols
// {8c..8c+7}; acc packed as f32x2 over column pairs.
static __device__ __forceinline__ void mmk(const float* A, const float* B,
                                           int r, int c, ull acc[4][4]) {
    #pragma unroll
    for (int i = 0; i < 16; i++) ((ull*)acc)[i] = 0ull;
    #pragma unroll
    for (int k4 = 0; k4 < 8; k4++) {
        float4 av[4];
        #pragma unroll
        for (int rho = 0; rho < 4; rho++)
            av[rho] = *(const float4*)(A + (r + 8 * rho) * PITCH + 4 * k4);
        ulonglong2 bv[4][2];
        #pragma unroll
        for (int kp = 0; kp < 4; kp++) {
            bv[kp][0] = *(const ulonglong2*)(B + (4 * k4 + kp) * PITCH + 8 * c);
            bv[kp][1] = *(const ulonglong2*)(B + (4 * k4 + kp) * PITCH + 8 * c + 4);
        }
        #pragma unroll
        for (int rho = 0; rho < 4; rho++) {
            const float* af = (const float*)&av[rho];
            #pragma unroll
            for (int kp = 0; kp < 4; kp++) {
                const ull a2 = pk2(af[kp], af[kp]);
                acc[rho][0] = fma2_(a2, bv[kp][0].x, acc[rho][0]);
                acc[rho][1] = fma2_(a2, bv[kp][0].y, acc[rho][1]);
                acc[rho][2] = fma2_(a2, bv[kp][1].x, acc[rho][2]);
                acc[rho][3] = fma2_(a2, bv[kp][1].y, acc[rho][3]);
            }
        }
    }
}

__global__ __launch_bounds__(256, 2) void ring_main(const float* __restrict__ X,
                                                    float* __restrict__ out) {
    extern __shared__ float smem[];
    float* Xs = smem;
    float* Wsm = smem + OFF_W;
    float* SL = smem + OFF_SL;
    float* SR = smem + OFF_SR;
    float* Asm = smem + OFF_AS;

    const int tid = threadIdx.x, w = tid >> 5, lane = tid & 31;
    const int r = lane >> 2, c = lane & 3;
    const int u = blockIdx.x >> 6;
    const int b0 = (blockIdx.x & 63) * 8;

    Xs[tid] = X[b0 * 32 + tid];
    __syncthreads();
    // W[b][p][c=(d0,d1)] = x[2p,d0] * x[2p+1,d1]
    #pragma unroll
    for (int e = tid; e < 512; e += 256) {
        const int bb = e >> 6, pp = (e >> 4) & 3, cc = e & 15;
        Wsm[e] = Xs[bb * 32 + 2 * pp * 4 + (cc >> 2)] *
                 Xs[bb * 32 + (2 * pp + 1) * 4 + (cc & 3)];
    }
    __syncthreads();

    // ---- S0 -> SL (pitch36), S1 -> SR (pitch36)
    build_stage<0>(u, 0, tid, Wsm, SL);
    build_stage<0>(u, 1, tid, Wsm, SR);
    __syncthreads();

    // ---- A = S0 @ S1, store to Asm (this warp's b)
    {
        ull acc[4][4];
        mmk(SL + w * SLOT, SR + w * SLOT, r, c, acc);
        float* dst = Asm + w * SLOT;
        #pragma unroll
        for (int rho = 0; rho < 4; rho++) {
            float4 o0, o1;
            upk2(acc[rho][0], o0.x, o0.y); upk2(acc[rho][1], o0.z, o0.w);
            upk2(acc[rho][2], o1.x, o1.y); upk2(acc[rho][3], o1.z, o1.w);
            *(float4*)(dst + (r + 8 * rho) * PITCH + 8 * c)     = o0;
            *(float4*)(dst + (r + 8 * rho) * PITCH + 8 * c + 4) = o1;
        }
    }
    __syncthreads();   // all warps done reading SL/SR

    // ---- S2 -> SL transposed (pitch33), S3 -> SR (pitch36)
    build_stage<1>(u, 2, tid, Wsm, SL);
    build_stage<0>(u, 3, tid, Wsm, SR);
    __syncthreads();

    // ---- D = S3 @ A ; out = sum_{j,k} S2[j,k] * D[k,j] = sum S2T[k][j]*D[k,j]
    {
        ull acc[4][4];
        mmk(SR + w * SLOT, Asm + w * SLOT, r, c, acc);
        const float* s2t = SL + w * SLOT;
        float pacc = 0.f;
        #pragma unroll
        for (int rho = 0; rho < 4; rho++) {
            const float* row = s2t + (r + 8 * rho) * 33 + 8 * c;
            #pragma unroll
            for (int gp = 0; gp < 4; gp++) {
                float d0, d1;
                upk2(acc[rho][gp], d0, d1);
                pacc = fmaf(d0, row[2 * gp], pacc);
                pacc = fmaf(d1, row[2 * gp + 1], pacc);
            }
        }
        #pragma unroll
        for (int o = 16; o; o >>= 1)
            pacc += __shfl_xor_sync(0xffffffffu, pacc, o);
        if (lane == 0) out[(b0 + w) * 64 + u] = pacc;
    }
}

extern "C" void kernel_launch(void* const* d_in, const int* in_sizes, int n_in,
                              void* d_out, int out_size) {
    const float* X = (const float*)d_in[0];
    const float* K = (const float*)d_in[1];
    if (in_sizes[0] != B_ * F_ * D_) {
        X = (const float*)d_in[1];
        K = (const float*)d_in[0];
    }
    cudaFuncSetAttribute(ring_main, cudaFuncAttributeMaxDynamicSharedMemorySize,
                         SMEM_FLOATS * 4);
    kk_precompute<<<256, 512>>>(K);
    ring_main<<<64 * 64, 256, SMEM_FLOATS * 4>>>(X, (float*)d_out);
}